// round 10
// baseline (speedup 1.0000x reference)
#include <cuda_runtime.h>
#include <cstdint>

// Conv2D: x[4096,4096] fp32, w[15,15], valid -> out[4082,4082] + bias.
//
// Round 9 = Round 8 occupancy + Round 4 crossbar economy.
//  - Input row loaded ONCE per t (hoisted out of the r loop), reused by all
//    RY=3 accumulator rows: 102 LDS.128/thread (R8 did 306 -> L1=88%).
//  - Register diet kept via two stages ACROSS the r loop:
//      stage 1: a[0..15] (4 LDS.128) -> all r, taps kx=0..8
//      stage 2: a[16..23] (2 LDS.128) -> all r, taps kx=9..14
//    Peak live ~95 regs -> still 5 CTAs/SM (20 warps/SM).
//  - 45-reg rotating weight window, statically indexed via unroll-by-3.
//  - cp.async staging; float2 stores (out rows only 8B-aligned).

#define HI 4096
#define WI 4096
#define KH 15
#define KW 15
#define OH (HI - KH + 1)   // 4082
#define OW (WI - KW + 1)   // 4082

#define TOX 128
#define TOY 24
#define RX  8
#define RY  3
#define NT  128

#define IN_ROWS (TOY + KH - 1)   // 38
#define PITCH   144              // floats per smem row

__global__ __launch_bounds__(NT, 5)
void conv2d_v9_kernel(const float* __restrict__ x,
                      const float* __restrict__ w,
                      const float* __restrict__ bias,
                      float* __restrict__ out)
{
    __shared__ float s_in[IN_ROWS][PITCH];   // 21.9 KB
    __shared__ float s_w[KH * KW];

    const int tid = threadIdx.x;
    const int ox0 = blockIdx.x * TOX;
    const int oy0 = blockIdx.y * TOY;

    // ---- Stage weights (strided: NT=128 < 225) ----
    #pragma unroll
    for (int i = tid; i < KH * KW; i += NT) s_w[i] = w[i];

    // ---- Stage input tile via cp.async (38 rows x 36 float4) ----
    // ox0 multiple of 128, WI%4==0 -> each float4 fully in- or out-of-range.
    #pragma unroll 2
    for (int i = tid; i < IN_ROWS * 36; i += NT) {
        const int r  = i / 36;
        const int c  = (i - r * 36) * 4;
        const int gy = oy0 + r;
        const int gx = ox0 + c;
        const uint32_t sa = (uint32_t)__cvta_generic_to_shared(&s_in[r][c]);
        if (gy < HI && gx < WI) {
            const float* gp = &x[(long)gy * WI + gx];
            asm volatile("cp.async.cg.shared.global [%0], [%1], 16;"
                         :: "r"(sa), "l"(gp) : "memory");
        } else {
            *reinterpret_cast<float4*>(&s_in[r][c]) = make_float4(0.f, 0.f, 0.f, 0.f);
        }
    }
    asm volatile("cp.async.commit_group;" ::: "memory");
    asm volatile("cp.async.wait_group 0;" ::: "memory");
    __syncthreads();

    const int tx = tid & 15;   // column group (8 wide)
    const int ty = tid >> 4;   // row strip (3 rows)

    float acc[RY][RX];
    #pragma unroll
    for (int r = 0; r < RY; ++r)
        #pragma unroll
        for (int j = 0; j < RX; ++j) acc[r][j] = 0.f;

    float wk[3][KW];           // rotating weight-row window, slot = ky % 3

    // t = 0..16, in 6 groups of 3 so slot (t-r)%3 == (c-r)%3 is compile-time.
    #pragma unroll 1
    for (int u = 0; u < 6; ++u) {
        #pragma unroll
        for (int c = 0; c < 3; ++c) {
            const int t = 3 * u + c;
            if (t < RY + KH - 1) {                 // skip t == 17
                if (t < KH) {                      // weight row t -> slot c
                    #pragma unroll
                    for (int kx = 0; kx < KW; ++kx)
                        wk[c][kx] = s_w[t * KW + kx];
                }

                const float* rp = &s_in[ty * RY + t][tx * RX];

                // ---- Stage 1: a[0..15] feeds taps kx=0..8 for ALL rows ----
                float a[16];
                #pragma unroll
                for (int q = 0; q < 4; ++q) {
                    const float4 v = *reinterpret_cast<const float4*>(rp + 4 * q);
                    a[4 * q + 0] = v.x; a[4 * q + 1] = v.y;
                    a[4 * q + 2] = v.z; a[4 * q + 3] = v.w;
                }
                #pragma unroll
                for (int r = 0; r < RY; ++r) {
                    if ((unsigned)(t - r) < (unsigned)KH) {     // ky in range
                        const int slot = ((c - r) % 3 + 3) % 3; // compile-time
                        #pragma unroll
                        for (int kx = 0; kx <= 8; ++kx) {
                            const float wv = wk[slot][kx];
                            #pragma unroll
                            for (int j = 0; j < RX; ++j)
                                acc[r][j] = fmaf(wv, a[kx + j], acc[r][j]);
                        }
                    }
                }

                // ---- Stage 2: a2 = a[16..23] feeds taps kx=9..14 ----
                float a2[8];
                #pragma unroll
                for (int q = 0; q < 2; ++q) {
                    const float4 v = *reinterpret_cast<const float4*>(rp + 16 + 4 * q);
                    a2[4 * q + 0] = v.x; a2[4 * q + 1] = v.y;
                    a2[4 * q + 2] = v.z; a2[4 * q + 3] = v.w;
                }
                #pragma unroll
                for (int r = 0; r < RY; ++r) {
                    if ((unsigned)(t - r) < (unsigned)KH) {
                        const int slot = ((c - r) % 3 + 3) % 3;
                        #pragma unroll
                        for (int kx = 9; kx < KW; ++kx) {
                            const float wv = wk[slot][kx];
                            #pragma unroll
                            for (int j = 0; j < RX; ++j) {
                                const int idx = kx + j;   // 9..21
                                const float av = (idx < 16) ? a[idx] : a2[idx - 16];
                                acc[r][j] = fmaf(wv, av, acc[r][j]);
                            }
                        }
                    }
                }
            }
        }
    }

    // ---- Epilogue: bias + float2 stores (8B-aligned: OW even, ox even) ----
    const float b = __ldg(&bias[0]);
    #pragma unroll
    for (int r = 0; r < RY; ++r) {
        const int oy = oy0 + ty * RY + r;
        if (oy >= OH) continue;
        float* orow = &out[(long)oy * OW];
        #pragma unroll
        for (int p = 0; p < 4; ++p) {
            const int ox = ox0 + tx * RX + 2 * p;
            if (ox + 1 < OW) {   // pair never straddles (OW even, ox even)
                float2 v = make_float2(acc[r][2 * p] + b, acc[r][2 * p + 1] + b);
                *reinterpret_cast<float2*>(&orow[ox]) = v;
            }
        }
    }
}

extern "C" void kernel_launch(void* const* d_in, const int* in_sizes, int n_in,
                              void* d_out, int out_size)
{
    const float* x    = (const float*)d_in[0];
    const float* w    = (const float*)d_in[1];
    const float* bias = (const float*)d_in[2];
    float* out        = (float*)d_out;

    dim3 grid((OW + TOX - 1) / TOX,   // 32
              (OH + TOY - 1) / TOY);  // 171
    conv2d_v9_kernel<<<grid, NT>>>(x, w, bias, out);
}

// round 12
// speedup vs baseline: 1.5653x; 1.5653x over previous
#include <cuda_runtime.h>
#include <cstdint>

// Conv2D: x[4096,4096] fp32, w[15,15], valid -> out[4082,4082] + bias.
//
// Round 12: legacy tensor cores via mma.sync (baseline PTX, works on
// compute_103 non-'a' target; tcgen05 is not available there).
//
// Banded-B GEMM per kernel row ky:
//   D[m,n] += sum_c A[m,c] * B[c,n],
//   A[m,c]  = tf32(X[oy(m)+ky, ox0+c])      (window of staged X tile)
//   B[c,n]  = tf32(W[ky, c-n]), 0 outside band 0<=c-n<15
// Warp: 16 oy x 32 ox = 4 x m16n8k8 n-tiles, 3 K-chunks each (K=24 padded).
// Adjacent n-tiles share 2/3 A chunks. CTA = 4 warps stacked in oy (64x32).
// XPITCH=68 (==4 mod 32) -> all fragment LDS provably bank-conflict-free.

typedef unsigned int u32;

#define HI 4096
#define WI 4096
#define KH 15
#define KW 15
#define OH 4082
#define OW 4082

#define NT  128
#define OYT 64
#define OXT 32
#define XR  (OYT + KH - 1)     // 78 staged rows
#define XP  68                 // pitch (floats); 68 % 32 == 4 -> conflict-free
#define XQ  12                 // float4 per staged row (48 cols >= 46 needed)

static __device__ __forceinline__ u32 f2tf(float f) {
    u32 r; asm("cvt.rna.tf32.f32 %0, %1;" : "=r"(r) : "f"(f)); return r;
}

__global__ __launch_bounds__(NT, 6)
void conv2d_hmma_kernel(const float* __restrict__ x, const float* __restrict__ w,
                        const float* __restrict__ bias, float* __restrict__ out)
{
    __shared__ float s_X[XR * XP];       // 21216 B (tf32-rounded after convert)
    __shared__ u32   s_B[KH * 24 * 8];   // 11520 B, banded B per ky, [c][n]

    const int tid  = threadIdx.x;
    const int wid  = tid >> 5;
    const int lane = tid & 31;
    const int g = lane >> 2;             // 0..7
    const int e = lane & 3;              // 0..3
    const int ox0 = blockIdx.x * OXT;
    const int oy0 = blockIdx.y * OYT;

    // ---- Build banded B (tf32) for all 15 ky ----
    for (int i = tid; i < KH * 24 * 8; i += NT) {
        const int ky = i / 192, r = i - ky * 192;
        const int c = r >> 3, n = r & 7;
        const int kx = c - n;
        s_B[i] = (kx >= 0 && kx < KW) ? f2tf(w[ky * KW + kx]) : 0u;
    }

    // ---- Stage X tile (78 x 48) via cp.async, zero-fill OOB ----
    for (int i = tid; i < XR * XQ; i += NT) {
        const int r = i / XQ, q = i - r * XQ;
        const int gy = oy0 + r, gx = ox0 + 4 * q;
        float* dst = &s_X[r * XP + 4 * q];
        const u32 sa = (u32)__cvta_generic_to_shared(dst);
        if (gy < HI && gx < WI)     // gx mult of 4, WI%4==0 -> full float4 ok
            asm volatile("cp.async.cg.shared.global [%0], [%1], 16;"
                         :: "r"(sa), "l"(&x[(long)gy * WI + gx]) : "memory");
        else
            *reinterpret_cast<float4*>(dst) = make_float4(0.f, 0.f, 0.f, 0.f);
    }
    asm volatile("cp.async.commit_group;" ::: "memory");
    asm volatile("cp.async.wait_group 0;" ::: "memory");
    __syncthreads();

    // ---- Round staged X to tf32 (RNA) in place ----
    for (int i = tid; i < XR * XQ; i += NT) {
        const int r = i / XQ, q = i - r * XQ;
        float4* p = reinterpret_cast<float4*>(&s_X[r * XP + 4 * q]);
        const float4 v = *p;
        *reinterpret_cast<uint4*>(p) =
            make_uint4(f2tf(v.x), f2tf(v.y), f2tf(v.z), f2tf(v.w));
    }
    __syncthreads();

    float d[4][4];
    #pragma unroll
    for (int j = 0; j < 4; ++j)
        #pragma unroll
        for (int k = 0; k < 4; ++k) d[j][k] = 0.f;

    const int rowb = (wid << 4) + g;     // warp's oy strip + group row

    // ---- Main loop: 15 ky, 12 HMMA each ----
    #pragma unroll 1
    for (int ky = 0; ky < KH; ++ky) {
        const u32* r0 = reinterpret_cast<const u32*>(&s_X[(rowb + ky) * XP]);
        const u32* r1 = r0 + 8 * XP;
        u32 A[6][4];
        #pragma unroll
        for (int t = 0; t < 6; ++t) {    // A chunk t covers cols 8t..8t+7
            A[t][0] = r0[8 * t + e];     A[t][1] = r1[8 * t + e];
            A[t][2] = r0[8 * t + e + 4]; A[t][3] = r1[8 * t + e + 4];
        }
        const u32* Bk = &s_B[ky * 192];
        u32 B[3][2];
        #pragma unroll
        for (int s = 0; s < 3; ++s) {    // B chunk s covers c' 8s..8s+7
            B[s][0] = Bk[(8 * s + e) * 8 + g];
            B[s][1] = Bk[(8 * s + e + 4) * 8 + g];
        }
        #pragma unroll
        for (int j = 0; j < 4; ++j)      // n-tile j uses A chunks j..j+2
            #pragma unroll
            for (int s = 0; s < 3; ++s)
                asm volatile(
                    "mma.sync.aligned.m16n8k8.row.col.f32.tf32.tf32.f32 "
                    "{%0,%1,%2,%3}, {%4,%5,%6,%7}, {%8,%9}, {%0,%1,%2,%3};"
                    : "+f"(d[j][0]), "+f"(d[j][1]), "+f"(d[j][2]), "+f"(d[j][3])
                    : "r"(A[j+s][0]), "r"(A[j+s][1]), "r"(A[j+s][2]), "r"(A[j+s][3]),
                      "r"(B[s][0]), "r"(B[s][1]));
    }

    // ---- Epilogue: bias + float2 stores (out rows only 8B-aligned) ----
    const float b = __ldg(&bias[0]);
    const int oyA = oy0 + rowb;          // row g of this warp's tile
    const int oyB = oyA + 8;             // row g+8
    #pragma unroll
    for (int j = 0; j < 4; ++j) {
        const int ox = ox0 + 8 * j + 2 * e;
        if (ox + 1 < OW) {               // ox even, OW even -> no straddle
            if (oyA < OH)
                *reinterpret_cast<float2*>(&out[(long)oyA * OW + ox]) =
                    make_float2(d[j][0] + b, d[j][1] + b);
            if (oyB < OH)
                *reinterpret_cast<float2*>(&out[(long)oyB * OW + ox]) =
                    make_float2(d[j][2] + b, d[j][3] + b);
        }
    }
}

extern "C" void kernel_launch(void* const* d_in, const int* in_sizes, int n_in,
                              void* d_out, int out_size)
{
    const float* x    = (const float*)d_in[0];
    const float* w    = (const float*)d_in[1];
    const float* bias = (const float*)d_in[2];
    float* out        = (float*)d_out;

    dim3 grid((OW + OXT - 1) / OXT,   // 128
              (OH + OYT - 1) / OYT);  // 64
    conv2d_hmma_kernel<<<grid, NT>>>(x, w, bias, out);
}